// round 5
// baseline (speedup 1.0000x reference)
#include <cuda_runtime.h>

#define N_IMG 8
#define C_IN  256
#define C_OUT 256
#define H_DIM 64
#define W_DIM 64
#define HW    4096
#define GROUPS 32
#define EPS_GN 1e-5f
#define CK    (C_IN * 9)   // 2304

#define ROWP  68           // padded row stride (floats) for k-major val tile
#define CHF   (9 * ROWP)   // floats per channel tile = 612
#define CPB   4            // channels per smem buffer

__device__ __forceinline__ unsigned long long pack2(float lo, float hi) {
    unsigned long long r;
    asm("mov.b64 %0, {%1, %2};" : "=l"(r) : "f"(lo), "f"(hi));
    return r;
}

// Scratch (static device globals; no runtime allocation)
__device__ float4 g_T[N_IMG * HW];        // per-pixel 2x2 transform (t00,t01,t10,t11)
__device__ float  g_wT[CK * C_OUT];       // dcn weights transposed: [c*9+k][o]
__device__ float2 g_stats[N_IMG * GROUPS];// (mu, rsigma) per (n, group)

// ---------------------------------------------------------------------------
// Kernel 0: transpose w_dcn [o][c][k] -> g_wT [c*9+k][o] for coalesced reads
// ---------------------------------------------------------------------------
__global__ void k_transpose_w(const float* __restrict__ w) {
    int i = blockIdx.x * 256 + threadIdx.x;          // i = o*CK + ck
    if (i >= C_OUT * CK) return;
    int o  = i / CK;
    int ck = i - o * CK;
    g_wT[ck * C_OUT + o] = w[i];
}

// ---------------------------------------------------------------------------
// Kernel 1: tm = conv3x3(x, w_tm) + b_tm  -> store T (4 floats) per pixel.
// Packed f32x2 accumulation: t01 = (t0,t1), t23 = (t2,t3).
// ---------------------------------------------------------------------------
__global__ void __launch_bounds__(256) k_offsets(const float* __restrict__ x,
                                                 const float* __restrict__ w_tm,
                                                 const float* __restrict__ b_tm) {
    __shared__ unsigned long long ws01[CK];          // (w_j0, w_j1) per ck
    __shared__ unsigned long long ws23[CK];          // (w_j2, w_j3) per ck
    int tid = threadIdx.x;
    for (int i = tid; i < CK; i += 256) {
        ws01[i] = pack2(w_tm[i],          w_tm[CK + i]);
        ws23[i] = pack2(w_tm[2 * CK + i], w_tm[3 * CK + i]);
    }
    __syncthreads();

    int P  = blockIdx.x * 256 + tid;                 // flat pixel
    int n  = P >> 12;
    int y  = (P >> 6) & 63;
    int xc = P & 63;

    unsigned long long t01 = pack2(__ldg(b_tm + 0), __ldg(b_tm + 1));
    unsigned long long t23 = pack2(__ldg(b_tm + 2), __ldg(b_tm + 3));

    int  doff[9];
    bool vld[9];
#pragma unroll
    for (int k = 0; k < 9; k++) {
        int dy = k / 3 - 1, dx = k % 3 - 1;
        int yy = y + dy, xx = xc + dx;
        vld[k]  = (yy >= 0) && (yy < H_DIM) && (xx >= 0) && (xx < W_DIM);
        doff[k] = dy * W_DIM + dx;
    }

    const float* xp = x + ((size_t)n * C_IN) * HW + y * W_DIM + xc;
    for (int c = 0; c < C_IN; c++) {
        const float* xpc = xp + c * HW;
#pragma unroll
        for (int k = 0; k < 9; k++) {
            float v = vld[k] ? __ldg(xpc + doff[k]) : 0.0f;
            unsigned long long vv;
            asm("mov.b64 %0, {%1, %1};" : "=l"(vv) : "f"(v));
            asm("fma.rn.f32x2 %0, %1, %2, %0;" : "+l"(t01) : "l"(vv), "l"(ws01[c * 9 + k]));
            asm("fma.rn.f32x2 %0, %1, %2, %0;" : "+l"(t23) : "l"(vv), "l"(ws23[c * 9 + k]));
        }
    }
    float t0, t1, t2, t3;
    asm("mov.b64 {%0, %1}, %2;" : "=f"(t0), "=f"(t1) : "l"(t01));
    asm("mov.b64 {%0, %1}, %2;" : "=f"(t2), "=f"(t3) : "l"(t23));
    g_T[P] = make_float4(t0, t1, t2, t3);
}

// ---------------------------------------------------------------------------
// Kernel 2: deformable conv. Block = one image row (64 px), 512 threads:
// thread = (o = tid&255, half = tid>>8 covering 32 px). Implicit-im2col GEMM
// with packed f32x2 FMA, k-major smem tiles, 4 channels per buffer.
// Register budget ~90 (acc 32 + W 18 + cached params) -> no spills.
// ---------------------------------------------------------------------------
__global__ void __launch_bounds__(512, 1) k_deform(const float* __restrict__ x,
                                                   float* __restrict__ out) {
    __shared__ int4   s_idx[576];             // per (p,k): 4 clamped gather indices
    __shared__ float4 s_w[576];               // per (p,k): 4 bilinear weights (0 if OOB)
    __shared__ float  s_val[2][CPB * CHF];    // double-buffered, 4 channels per buffer

    int tid  = threadIdx.x;
    int half = tid >> 8;                      // 0: px 0-31, 1: px 32-63
    int o    = tid & 255;
    int R = blockIdx.x;                       // row id = n*64 + y
    int n = R >> 6;
    int y = R & 63;

    // --- precompute bilinear params for all 64 pixels x 9 taps ---
    for (int v = tid; v < 576; v += 512) {
        int p = v / 9, k = v - p * 9;
        float4 T = g_T[R * 64 + p];
        float dy = (float)(k / 3 - 1), dx = (float)(k % 3 - 1);
        float py = (float)y + T.x * dy + T.y * dx;
        float px = (float)p + T.z * dy + T.w * dx;
        float y0f = floorf(py), x0f = floorf(px);
        float wy = py - y0f, wx = px - x0f;
        int iy0 = (int)y0f, ix0 = (int)x0f;
        int iy1 = iy0 + 1,  ix1 = ix0 + 1;
        bool vy0 = (iy0 >= 0) && (iy0 <= H_DIM - 1);
        bool vy1 = (iy1 >= 0) && (iy1 <= H_DIM - 1);
        bool vx0 = (ix0 >= 0) && (ix0 <= W_DIM - 1);
        bool vx1 = (ix1 >= 0) && (ix1 <= W_DIM - 1);
        int cy0 = min(H_DIM - 1, max(0, iy0)), cy1 = min(H_DIM - 1, max(0, iy1));
        int cx0 = min(W_DIM - 1, max(0, ix0)), cx1 = min(W_DIM - 1, max(0, ix1));
        float w00 = (vy0 && vx0) ? (1.f - wy) * (1.f - wx) : 0.f;
        float w01 = (vy0 && vx1) ? (1.f - wy) * wx         : 0.f;
        float w10 = (vy1 && vx0) ? wy * (1.f - wx)         : 0.f;
        float w11 = (vy1 && vx1) ? wy * wx                 : 0.f;
        s_idx[v] = make_int4(cy0 * W_DIM + cx0, cy0 * W_DIM + cx1,
                             cy1 * W_DIM + cx0, cy1 * W_DIM + cx1);
        s_w[v]   = make_float4(w00, w01, w10, w11);
    }
    __syncthreads();

    // builder assignments: thread owns entry tid, plus tid+512 if tid<64.
    // k-major destination: offset = k*ROWP + p
    bool has2 = (tid < 64);
    int v0 = tid, v1 = has2 ? tid + 512 : 0;
    int o0 = (v0 % 9) * ROWP + v0 / 9;
    int o1 = (v1 % 9) * ROWP + v1 / 9;
    int4   id0 = s_idx[v0], id1 = s_idx[v1];
    float4 wt0 = s_w[v0],   wt1 = s_w[v1];

    const float* xb = x + (size_t)n * C_IN * HW;
    unsigned long long acc2[16];              // 16 packed fp32x2 = 32 px accumulators
#pragma unroll
    for (int i = 0; i < 16; i++) acc2[i] = 0ULL;

    // build channels 0..3 into buffer 0
#pragma unroll
    for (int u = 0; u < CPB; u++) {
        const float* xp = xb + u * HW;
        float* dst = s_val[0] + u * CHF;
        dst[o0] = wt0.x * __ldg(xp + id0.x) + wt0.y * __ldg(xp + id0.y)
                + wt0.z * __ldg(xp + id0.z) + wt0.w * __ldg(xp + id0.w);
        if (has2)
            dst[o1] = wt1.x * __ldg(xp + id1.x) + wt1.y * __ldg(xp + id1.y)
                    + wt1.z * __ldg(xp + id1.z) + wt1.w * __ldg(xp + id1.w);
    }
    __syncthreads();

    const float* wb = g_wT + o;               // coalesced weight reads
    for (int cc = 0; cc < C_IN / CPB; cc++) {
        int cur = cc & 1;
        if (cc + 1 < C_IN / CPB) {            // build next 4 channels
            int nb = cur ^ 1;
#pragma unroll
            for (int u = 0; u < CPB; u++) {
                const float* xp = xb + (CPB * (cc + 1) + u) * HW;
                float* dst = s_val[nb] + u * CHF;
                dst[o0] = wt0.x * __ldg(xp + id0.x) + wt0.y * __ldg(xp + id0.y)
                        + wt0.z * __ldg(xp + id0.z) + wt0.w * __ldg(xp + id0.w);
                if (has2)
                    dst[o1] = wt1.x * __ldg(xp + id1.x) + wt1.y * __ldg(xp + id1.y)
                            + wt1.z * __ldg(xp + id1.z) + wt1.w * __ldg(xp + id1.w);
            }
        }
        // consume 4 channels from current buffer (this thread's 32 pixels)
#pragma unroll
        for (int u = 0; u < CPB; u++) {
            const float* wp = wb + (size_t)(CPB * cc + u) * 9 * C_OUT;
            unsigned long long W[9];
#pragma unroll
            for (int k = 0; k < 9; k++) {
                float w = __ldg(wp + k * C_OUT);
                asm("mov.b64 %0, {%1, %1};" : "=l"(W[k]) : "f"(w));
            }
            const float* vb = s_val[cur] + u * CHF + half * 32;
#pragma unroll
            for (int k = 0; k < 9; k++) {
                const ulonglong2* row = (const ulonglong2*)(vb + k * ROWP);
#pragma unroll
                for (int i = 0; i < 8; i++) {
                    ulonglong2 v = row[i];    // 4 pixels, pre-packed as 2x f32x2
                    asm("fma.rn.f32x2 %0, %1, %2, %0;"
                        : "+l"(acc2[2 * i])     : "l"(v.x), "l"(W[k]));
                    asm("fma.rn.f32x2 %0, %1, %2, %0;"
                        : "+l"(acc2[2 * i + 1]) : "l"(v.y), "l"(W[k]));
                }
            }
        }
        __syncthreads();
    }

    // epilogue: thread (o, half) owns 32 contiguous output floats
    float4* op = (float4*)(out + ((size_t)(n * C_OUT + o)) * HW + y * W_DIM + half * 32);
#pragma unroll
    for (int i = 0; i < 8; i++) {
        union { unsigned long long u; float2 f; } a, b;
        a.u = acc2[2 * i];
        b.u = acc2[2 * i + 1];
        op[i] = make_float4(a.f.x, a.f.y, b.f.x, b.f.y);
    }
}

// ---------------------------------------------------------------------------
// Kernel 3: GroupNorm statistics. One block per (n, group): 8 ch x 4096 px.
// ---------------------------------------------------------------------------
__global__ void __launch_bounds__(256) k_gn_stats(const float* __restrict__ out) {
    int gidx = blockIdx.x;                                // n*32 + g
    const float4* p = (const float4*)(out + (size_t)gidx * 8 * HW);
    int tid = threadIdx.x;
    float s = 0.f, s2 = 0.f;
    for (int i = tid; i < 8 * HW / 4; i += 256) {
        float4 v = p[i];
        s  += (v.x + v.y) + (v.z + v.w);
        s2  = fmaf(v.x, v.x, fmaf(v.y, v.y, fmaf(v.z, v.z, fmaf(v.w, v.w, s2))));
    }
    __shared__ float sh[2][8];
#pragma unroll
    for (int off = 16; off; off >>= 1) {
        s  += __shfl_down_sync(0xffffffffu, s, off);
        s2 += __shfl_down_sync(0xffffffffu, s2, off);
    }
    int warp = tid >> 5;
    if ((tid & 31) == 0) { sh[0][warp] = s; sh[1][warp] = s2; }
    __syncthreads();
    if (tid == 0) {
        float a = 0.f, b = 0.f;
#pragma unroll
        for (int i = 0; i < 8; i++) { a += sh[0][i]; b += sh[1][i]; }
        const float inv = 1.f / (8.f * HW);
        float mu  = a * inv;
        float var = b * inv - mu * mu;
        g_stats[gidx] = make_float2(mu, rsqrtf(var + EPS_GN));
    }
}

// ---------------------------------------------------------------------------
// Kernel 4: normalize + affine + ReLU, in place on d_out.
// ---------------------------------------------------------------------------
__global__ void __launch_bounds__(256) k_gn_norm(float* __restrict__ out,
                                                 const float* __restrict__ gamma,
                                                 const float* __restrict__ beta) {
    int f = blockIdx.x * 256 + threadIdx.x;               // float4 index
    int plane = f >> 10;                                  // 1024 float4 per channel plane
    int c = plane & 255;
    float2 st = g_stats[plane >> 3];                      // n*32 + c/8
    float ga = __ldg(gamma + c) * st.y;
    float be = __ldg(beta + c) - st.x * ga;
    float4* p = (float4*)out + f;
    float4 v = *p;
    v.x = fmaxf(fmaf(v.x, ga, be), 0.f);
    v.y = fmaxf(fmaf(v.y, ga, be), 0.f);
    v.z = fmaxf(fmaf(v.z, ga, be), 0.f);
    v.w = fmaxf(fmaf(v.w, ga, be), 0.f);
    *p = v;
}

// ---------------------------------------------------------------------------
extern "C" void kernel_launch(void* const* d_in, const int* in_sizes, int n_in,
                              void* d_out, int out_size) {
    (void)in_sizes; (void)n_in; (void)out_size;
    const float* x     = (const float*)d_in[0];
    const float* w_tm  = (const float*)d_in[1];
    const float* b_tm  = (const float*)d_in[2];
    const float* w_dcn = (const float*)d_in[3];
    const float* gamma = (const float*)d_in[4];
    const float* beta  = (const float*)d_in[5];
    float* out = (float*)d_out;

    k_transpose_w<<<(C_OUT * CK + 255) / 256, 256>>>(w_dcn);
    k_offsets<<<N_IMG * HW / 256, 256>>>(x, w_tm, b_tm);
    k_deform<<<N_IMG * H_DIM, 512>>>(x, out);
    k_gn_stats<<<N_IMG * GROUPS, 256>>>(out);
    k_gn_norm<<<(N_IMG * C_OUT * HW / 4) / 256, 256>>>(out, gamma, beta);
}

// round 7
// speedup vs baseline: 2.3713x; 2.3713x over previous
#include <cuda_runtime.h>
#include <cuda_bf16.h>
#include <cstdint>

#define N_IMG 8
#define C_IN  256
#define C_OUT 256
#define H_DIM 64
#define W_DIM 64
#define HW    4096
#define GROUPS 32
#define EPS_GN 1e-5f
#define CK    (C_IN * 9)   // 2304
#define NT    36           // K-tiles
#define KT    64           // ck per tile

// ---- dynamic smem layout for k_deform (bytes) ----
#define SM_IDX   0                    // ushort4[576] = 4608
#define SM_WGT   4608                 // float4[576]  = 9216  -> 13824
#define SM_A     14336                // Ah 8192 + Al 8192 = 16384
#define SM_B     30720                // Bh 32768 + Bl 32768 = 65536
#define SM_TOTAL 96256
#define SM_OUT   SM_A                 // epilogue reuses A+B region (69632 <= 81920)
#define OSTR     68                   // f32 stride for out staging rows

static __device__ __forceinline__ uint32_t smem_u32(const void* p) {
    uint32_t a;
    asm("{ .reg .u64 t; cvta.to.shared.u64 t, %1; cvt.u32.u64 %0, t; }" : "=r"(a) : "l"(p));
    return a;
}
static __device__ __forceinline__ void lds32(uint32_t& d, uint32_t a) {
    asm volatile("ld.shared.b32 %0, [%1];" : "=r"(d) : "r"(a));
}
static __device__ __forceinline__ void ldmx4(uint32_t* r, uint32_t a) {
    asm volatile("ldmatrix.sync.aligned.m8n8.x4.shared.b16 {%0,%1,%2,%3}, [%4];"
                 : "=r"(r[0]), "=r"(r[1]), "=r"(r[2]), "=r"(r[3]) : "r"(a));
}
static __device__ __forceinline__ void mma16816(float* c, const uint32_t* a,
                                                uint32_t b0, uint32_t b1) {
    asm volatile("mma.sync.aligned.m16n8k16.row.col.f32.bf16.bf16.f32 "
                 "{%0,%1,%2,%3}, {%4,%5,%6,%7}, {%8,%9}, {%0,%1,%2,%3};"
                 : "+f"(c[0]), "+f"(c[1]), "+f"(c[2]), "+f"(c[3])
                 : "r"(a[0]), "r"(a[1]), "r"(a[2]), "r"(a[3]), "r"(b0), "r"(b1));
}
__device__ __forceinline__ unsigned long long pack2(float lo, float hi) {
    unsigned long long r;
    asm("mov.b64 %0, {%1, %2};" : "=l"(r) : "f"(lo), "f"(hi));
    return r;
}

// Scratch (static device globals; no runtime allocation)
__device__ float4 g_T[N_IMG * HW];                       // per-pixel 2x2 transform
__device__ __align__(16) __nv_bfloat16 g_wh[C_OUT * CK]; // weight hi  [o][ck]
__device__ __align__(16) __nv_bfloat16 g_wl[C_OUT * CK]; // weight lo  [o][ck]
__device__ float2 g_stats[N_IMG * GROUPS];               // (mu, rsigma)

// ---------------------------------------------------------------------------
// Kernel 0: split w_dcn into bf16 hi/lo, same [o][ck] layout
// ---------------------------------------------------------------------------
__global__ void k_prep_w(const float* __restrict__ w) {
    int i = blockIdx.x * 256 + threadIdx.x;
    if (i >= C_OUT * CK) return;
    float v = w[i];
    __nv_bfloat16 h = __float2bfloat16(v);
    __nv_bfloat16 l = __float2bfloat16(v - __bfloat162float(h));
    g_wh[i] = h;
    g_wl[i] = l;
}

// ---------------------------------------------------------------------------
// Kernel 1: tm = conv3x3(x, w_tm) + b_tm  -> store T per pixel (fp32, f32x2)
// ---------------------------------------------------------------------------
__global__ void __launch_bounds__(256) k_offsets(const float* __restrict__ x,
                                                 const float* __restrict__ w_tm,
                                                 const float* __restrict__ b_tm) {
    __shared__ unsigned long long ws01[CK];
    __shared__ unsigned long long ws23[CK];
    int tid = threadIdx.x;
    for (int i = tid; i < CK; i += 256) {
        ws01[i] = pack2(w_tm[i],          w_tm[CK + i]);
        ws23[i] = pack2(w_tm[2 * CK + i], w_tm[3 * CK + i]);
    }
    __syncthreads();

    int P  = blockIdx.x * 256 + tid;
    int n  = P >> 12;
    int y  = (P >> 6) & 63;
    int xc = P & 63;

    unsigned long long t01 = pack2(__ldg(b_tm + 0), __ldg(b_tm + 1));
    unsigned long long t23 = pack2(__ldg(b_tm + 2), __ldg(b_tm + 3));

    int  doff[9];
    bool vld[9];
#pragma unroll
    for (int k = 0; k < 9; k++) {
        int dy = k / 3 - 1, dx = k % 3 - 1;
        int yy = y + dy, xx = xc + dx;
        vld[k]  = (yy >= 0) && (yy < H_DIM) && (xx >= 0) && (xx < W_DIM);
        doff[k] = dy * W_DIM + dx;
    }

    const float* xp = x + ((size_t)n * C_IN) * HW + y * W_DIM + xc;
    for (int c = 0; c < C_IN; c++) {
        const float* xpc = xp + c * HW;
#pragma unroll
        for (int k = 0; k < 9; k++) {
            float v = vld[k] ? __ldg(xpc + doff[k]) : 0.0f;
            unsigned long long vv;
            asm("mov.b64 %0, {%1, %1};" : "=l"(vv) : "f"(v));
            asm("fma.rn.f32x2 %0, %1, %2, %0;" : "+l"(t01) : "l"(vv), "l"(ws01[c * 9 + k]));
            asm("fma.rn.f32x2 %0, %1, %2, %0;" : "+l"(t23) : "l"(vv), "l"(ws23[c * 9 + k]));
        }
    }
    float t0, t1, t2, t3;
    asm("mov.b64 {%0, %1}, %2;" : "=f"(t0), "=f"(t1) : "l"(t01));
    asm("mov.b64 {%0, %1}, %2;" : "=f"(t2), "=f"(t3) : "l"(t23));
    g_T[P] = make_float4(t0, t1, t2, t3);
}

// ---------------------------------------------------------------------------
// Kernel 2: deformable conv as warp-MMA bf16-split GEMM (HMMA path).
// CTA = one image row (64 px) x N=256. K=2304 in 36 tiles of 64 ck.
// D = Ah*Bh + Al*Bh + Ah*Bl, fp32 accumulators in registers.
// 16 warps: warp tile 16(M) x 64(N); mw = wid&3, nw = wid>>2.
// ---------------------------------------------------------------------------
__global__ void __launch_bounds__(512, 1) k_deform(const float* __restrict__ x,
                                                   float* __restrict__ out) {
    extern __shared__ char smem[];
    const uint32_t sbase = smem_u32(smem);
    int tid  = threadIdx.x;
    int wid  = tid >> 5;
    int lane = tid & 31;
    int blk  = blockIdx.x;                 // n*64 + y
    int n    = blk >> 6;
    int y0   = blk & 63;

    // ---- bilinear params for 64 px x 9 taps ----
    ushort4* s_idx = (ushort4*)(smem + SM_IDX);
    float4*  s_wgt = (float4*)(smem + SM_WGT);
    for (int v = tid; v < 576; v += 512) {
        int p = v / 9, k = v - p * 9;
        float4 T = g_T[(size_t)blk * 64 + p];
        float dy = (float)(k / 3 - 1), dx = (float)(k % 3 - 1);
        float py = (float)y0 + T.x * dy + T.y * dx;
        float px = (float)p  + T.z * dy + T.w * dx;
        float y0f = floorf(py), x0f = floorf(px);
        float wy = py - y0f, wx = px - x0f;
        int iy0 = (int)y0f, ix0 = (int)x0f;
        int iy1 = iy0 + 1,  ix1 = ix0 + 1;
        bool vy0 = (iy0 >= 0) && (iy0 <= H_DIM - 1);
        bool vy1 = (iy1 >= 0) && (iy1 <= H_DIM - 1);
        bool vx0 = (ix0 >= 0) && (ix0 <= W_DIM - 1);
        bool vx1 = (ix1 >= 0) && (ix1 <= W_DIM - 1);
        int cy0 = min(H_DIM - 1, max(0, iy0)), cy1 = min(H_DIM - 1, max(0, iy1));
        int cx0 = min(W_DIM - 1, max(0, ix0)), cx1 = min(W_DIM - 1, max(0, ix1));
        float w00 = (vy0 && vx0) ? (1.f - wy) * (1.f - wx) : 0.f;
        float w01 = (vy0 && vx1) ? (1.f - wy) * wx         : 0.f;
        float w10 = (vy1 && vx0) ? wy * (1.f - wx)         : 0.f;
        float w11 = (vy1 && vx1) ? wy * wx                 : 0.f;
        s_idx[v] = make_ushort4((unsigned short)(cy0 * W_DIM + cx0),
                                (unsigned short)(cy0 * W_DIM + cx1),
                                (unsigned short)(cy1 * W_DIM + cx0),
                                (unsigned short)(cy1 * W_DIM + cx1));
        s_wgt[v] = make_float4(w00, w01, w10, w11);
    }
    __syncthreads();

    const float* xb = x + (size_t)n * C_IN * HW;

    // builder mapping: px = tid&63, ck-group (8 ck) = tid>>6
    const int bpx  = tid & 63;
    const int bckg = tid >> 6;
    const int bpar = bpx * 9;
    const uint32_t abyte = (uint32_t)(bpx * 128 + bckg * 16);
    const uint32_t asw   = abyte ^ ((abyte >> 3) & 0x70);

    // consumer mapping
    const int mw = wid & 3, nw = wid >> 2;
    const int arow = mw * 16 + (lane & 15);                 // A row for ldmatrix
    const uint32_t aswx = (uint32_t)((arow & 7) << 4);
    const uint32_t abase0 = (uint32_t)(arow * 128 + ((lane >> 4) << 4));
    const int nrow0 = nw * 64 + (lane >> 2);                // B row base (n)
    const uint32_t kpb = (uint32_t)((lane & 3) << 2);       // k-pair byte offset

    float acc[8][4];
#pragma unroll
    for (int f = 0; f < 8; f++)
#pragma unroll
        for (int r = 0; r < 4; r++) acc[f][r] = 0.f;

    for (int t = 0; t < NT; ++t) {
        const int ckb = t * KT;

        // ---- build A tile (hi/lo): this thread's 8 ck values for pixel bpx ----
        {
            uint32_t hr[4], lr[4];
#pragma unroll
            for (int e = 0; e < 4; ++e) {
                float vv[2];
#pragma unroll
                for (int q = 0; q < 2; ++q) {
                    int ck = ckb + bckg * 8 + e * 2 + q;
                    int c = ck / 9;
                    int k = ck - 9 * c;
                    ushort4 id = s_idx[bpar + k];
                    float4  w  = s_wgt[bpar + k];
                    const float* xp = xb + c * HW;
                    vv[q] = w.x * __ldg(xp + id.x) + w.y * __ldg(xp + id.y)
                          + w.z * __ldg(xp + id.z) + w.w * __ldg(xp + id.w);
                }
                __nv_bfloat16 h0 = __float2bfloat16(vv[0]);
                __nv_bfloat16 h1 = __float2bfloat16(vv[1]);
                __nv_bfloat16 l0 = __float2bfloat16(vv[0] - __bfloat162float(h0));
                __nv_bfloat16 l1 = __float2bfloat16(vv[1] - __bfloat162float(h1));
                hr[e] = (uint32_t)__bfloat16_as_ushort(h0)
                      | ((uint32_t)__bfloat16_as_ushort(h1) << 16);
                lr[e] = (uint32_t)__bfloat16_as_ushort(l0)
                      | ((uint32_t)__bfloat16_as_ushort(l1) << 16);
            }
            *(uint4*)(smem + SM_A + asw)        = make_uint4(hr[0], hr[1], hr[2], hr[3]);
            *(uint4*)(smem + SM_A + 8192 + asw) = make_uint4(lr[0], lr[1], lr[2], lr[3]);
        }

        // ---- load B tile (hi/lo): 256 o x 64 ck, swizzled ----
#pragma unroll
        for (int r = 0; r < 4; ++r) {
            int q = tid + (r << 9);            // 0..2047
            int o = q >> 3;
            int j = q & 7;
            size_t src = (size_t)o * CK + ckb + j * 8;
            uint4 dh = __ldg((const uint4*)(g_wh + src));
            uint4 dl = __ldg((const uint4*)(g_wl + src));
            uint32_t byte = (uint32_t)(o * 128 + j * 16);
            uint32_t sw = byte ^ ((byte >> 3) & 0x70);
            *(uint4*)(smem + SM_B + sw)         = dh;
            *(uint4*)(smem + SM_B + 32768 + sw) = dl;
        }
        __syncthreads();

        // ---- consume: 4 k16 steps ----
#pragma unroll
        for (int s = 0; s < 4; ++s) {
            uint32_t ah[4], al[4];
            uint32_t aoff = (abase0 + (uint32_t)(s * 32)) ^ aswx;
            ldmx4(ah, sbase + SM_A + aoff);
            ldmx4(al, sbase + SM_A + 8192 + aoff);
#pragma unroll
            for (int f = 0; f < 8; ++f) {
                uint32_t bbyte = (uint32_t)((nrow0 + f * 8) * 128) + kpb + (uint32_t)(s * 32);
                uint32_t swx = (bbyte >> 3) & 0x70;    // depends only on n&7
                uint32_t a0 = (bbyte) ^ swx;
                uint32_t a1 = (bbyte + 16) ^ swx;
                uint32_t b0h, b1h, b0l, b1l;
                lds32(b0h, sbase + SM_B + a0);
                lds32(b1h, sbase + SM_B + a1);
                lds32(b0l, sbase + SM_B + 32768 + a0);
                lds32(b1l, sbase + SM_B + 32768 + a1);
                mma16816(acc[f], ah, b0h, b1h);
                mma16816(acc[f], al, b0h, b1h);
                mma16816(acc[f], ah, b0l, b1l);
            }
        }
        __syncthreads();
    }

    // ---- epilogue: stage to smem (o-major, px rows of 64, stride 68) ----
    float* so = (float*)(smem + SM_OUT);
    {
        int rowg = mw * 16 + (lane >> 2);
#pragma unroll
        for (int f = 0; f < 8; ++f) {
            int o = nw * 64 + f * 8 + ((lane & 3) << 1);
            so[o * OSTR + rowg]           = acc[f][0];
            so[(o + 1) * OSTR + rowg]     = acc[f][1];
            so[o * OSTR + rowg + 8]       = acc[f][2];
            so[(o + 1) * OSTR + rowg + 8] = acc[f][3];
        }
    }
    __syncthreads();

    float* ob = out + (size_t)n * C_OUT * HW + y0 * 64;
    for (int q = tid; q < 256 * 16; q += 512) {
        int o = q >> 4, ch = q & 15;
        float4 v = *(float4*)(so + o * OSTR + ch * 4);
        *(float4*)(ob + (size_t)o * HW + ch * 4) = v;
    }
}

// ---------------------------------------------------------------------------
// Kernel 3: GroupNorm statistics. One block per (n, group): 8 ch x 4096 px.
// ---------------------------------------------------------------------------
__global__ void __launch_bounds__(256) k_gn_stats(const float* __restrict__ out) {
    int gidx = blockIdx.x;
    const float4* p = (const float4*)(out + (size_t)gidx * 8 * HW);
    int tid = threadIdx.x;
    float s = 0.f, s2 = 0.f;
    for (int i = tid; i < 8 * HW / 4; i += 256) {
        float4 v = p[i];
        s  += (v.x + v.y) + (v.z + v.w);
        s2  = fmaf(v.x, v.x, fmaf(v.y, v.y, fmaf(v.z, v.z, fmaf(v.w, v.w, s2))));
    }
    __shared__ float sh[2][8];
#pragma unroll
    for (int off = 16; off; off >>= 1) {
        s  += __shfl_down_sync(0xffffffffu, s, off);
        s2 += __shfl_down_sync(0xffffffffu, s2, off);
    }
    int warp = tid >> 5;
    if ((tid & 31) == 0) { sh[0][warp] = s; sh[1][warp] = s2; }
    __syncthreads();
    if (tid == 0) {
        float a = 0.f, bsum = 0.f;
#pragma unroll
        for (int i = 0; i < 8; i++) { a += sh[0][i]; bsum += sh[1][i]; }
        const float inv = 1.f / (8.f * HW);
        float mu  = a * inv;
        float var = bsum * inv - mu * mu;
        g_stats[gidx] = make_float2(mu, rsqrtf(var + EPS_GN));
    }
}

// ---------------------------------------------------------------------------
// Kernel 4: normalize + affine + ReLU, in place on d_out.
// ---------------------------------------------------------------------------
__global__ void __launch_bounds__(256) k_gn_norm(float* __restrict__ out,
                                                 const float* __restrict__ gamma,
                                                 const float* __restrict__ beta) {
    int f = blockIdx.x * 256 + threadIdx.x;
    int plane = f >> 10;
    int c = plane & 255;
    float2 st = g_stats[plane >> 3];
    float ga = __ldg(gamma + c) * st.y;
    float be = __ldg(beta + c) - st.x * ga;
    float4* p = (float4*)out + f;
    float4 v = *p;
    v.x = fmaxf(fmaf(v.x, ga, be), 0.f);
    v.y = fmaxf(fmaf(v.y, ga, be), 0.f);
    v.z = fmaxf(fmaf(v.z, ga, be), 0.f);
    v.w = fmaxf(fmaf(v.w, ga, be), 0.f);
    *p = v;
}

// ---------------------------------------------------------------------------
extern "C" void kernel_launch(void* const* d_in, const int* in_sizes, int n_in,
                              void* d_out, int out_size) {
    (void)in_sizes; (void)n_in; (void)out_size;
    const float* x     = (const float*)d_in[0];
    const float* w_tm  = (const float*)d_in[1];
    const float* b_tm  = (const float*)d_in[2];
    const float* w_dcn = (const float*)d_in[3];
    const float* gamma = (const float*)d_in[4];
    const float* beta  = (const float*)d_in[5];
    float* out = (float*)d_out;

    cudaFuncSetAttribute(k_deform, cudaFuncAttributeMaxDynamicSharedMemorySize, SM_TOTAL);

    k_prep_w<<<(C_OUT * CK + 255) / 256, 256>>>(w_dcn);
    k_offsets<<<N_IMG * HW / 256, 256>>>(x, w_tm, b_tm);
    k_deform<<<N_IMG * H_DIM, 512, SM_TOTAL>>>(x, out);
    k_gn_stats<<<N_IMG * GROUPS, 256>>>(out);
    k_gn_norm<<<(N_IMG * C_OUT * HW / 4) / 256, 256>>>(out, gamma, beta);
}